// round 13
// baseline (speedup 1.0000x reference)
#include <cuda_runtime.h>
#include <cuda_bf16.h>
#include <math_constants.h>

#define BB 512
#define QQ 100
#define CC 81
#define VV 117
#define NQ (BB*QQ)

// Output layout (flattened tuple, float32):
// hoi_scores [B,Q,V] | obj_labels [B,Q] | sub_boxes [B,Q,4] | obj_boxes [B,Q,4] | keep [B,Q]
#define OFF_HOI  0ull
#define OFF_LAB  ((unsigned long long)NQ * VV)
#define OFF_SUB  (OFF_LAB + (unsigned long long)NQ)
#define OFF_OBJ  (OFF_SUB + (unsigned long long)NQ * 4)
#define OFF_KEEP (OFF_OBJ + (unsigned long long)NQ * 4)

#define MAXP (QQ*(QQ-1)/2)   // 4950 pair worklist worst case

// ---------------------------------------------------------------------------
// Fused kernel: one block (256 threads = 8 warps) per image.
// Phase 0: bit-pack cmat (binary) into shared, per block (L2-resident reads).
// Phase A: warp-per-query scoring + boxes (results kept in shared).
// Phase B: compacted-pair NMS (only same-label pairs evaluated).
// No device-global scratch: fully graph-replay-safe.
// ---------------------------------------------------------------------------
__global__ __launch_bounds__(256, 4)
void k_fused(const float* __restrict__ obj_logits,
             const float* __restrict__ verb_logits,
             const float* __restrict__ sub_in,
             const float* __restrict__ obj_in,
             const float* __restrict__ cmat,     // [V, C], values in {0,1}
             const int* __restrict__ ts,         // [B, 2] (h, w) int32
             float* __restrict__ out)
{
    const int b    = blockIdx.x;
    const int tid  = threadIdx.x;
    const int wid  = tid >> 5;
    const int lane = tid & 31;

    __shared__ unsigned cbits[CC][4];      // cmat column bitmasks: bit v of label c
    __shared__ float sh_max[QQ];
    __shared__ int   sh_lab[QQ];
    __shared__ float sh_box[QQ][8];        // scaled xyxy: [0..3]=sub, [4..7]=obj
    __shared__ short rpart[2][QQ];
    __shared__ int   s_orig[QQ];
    __shared__ int   r_lab[QQ];
    __shared__ float r_s[5][QQ];           // sorted sub: x1,y1,x2,y2,area
    __shared__ float r_o[5][QQ];           // sorted obj
    __shared__ unsigned lmask[CC][4];      // per-label bitmask of sorted positions
    __shared__ unsigned supmat[QQ][4];
    __shared__ unsigned suppw[4];
    __shared__ int npairs;
    __shared__ ushort2 plist[MAXP];

    // zero-init tables used later
    for (int t = tid; t < CC * 4; t += 256) ((unsigned*)lmask)[t] = 0u;
    for (int t = tid; t < QQ * 4; t += 256) ((unsigned*)supmat)[t] = 0u;
    if (tid == 0) npairs = 0;

    // ---- Phase 0: bit-pack cmat columns (warp w handles labels w, w+8, ...) ----
    for (int c = wid; c < CC; c += 8) {
        unsigned w0, w1, w2, w3;
        {
            int v = lane;          float f = cmat[(size_t)v * CC + c];
            w0 = __ballot_sync(0xffffffffu, f != 0.0f);
        }
        {
            int v = 32 + lane;     float f = cmat[(size_t)v * CC + c];
            w1 = __ballot_sync(0xffffffffu, f != 0.0f);
        }
        {
            int v = 64 + lane;     float f = cmat[(size_t)v * CC + c];
            w2 = __ballot_sync(0xffffffffu, f != 0.0f);
        }
        {
            int v = 96 + lane;
            float f = (v < VV) ? cmat[(size_t)v * CC + c] : 0.0f;
            w3 = __ballot_sync(0xffffffffu, f != 0.0f);
        }
        if (lane == 0) {
            cbits[c][0] = w0; cbits[c][1] = w1; cbits[c][2] = w2; cbits[c][3] = w3;
        }
    }

    const float img_h = (float)ts[b * 2 + 0];
    const float img_w = (float)ts[b * 2 + 1];
    __syncthreads();

    // ---- Phase A: warp-per-query scoring + boxes ----
    for (int q = wid; q < QQ; q += 8) {
        const int gq = b * QQ + q;

        // softmax over 81 logits; max/argmax over first 80
        const float* ol = obj_logits + (size_t)gq * CC;
        float l0 = ol[lane];
        float l1 = (lane + 32 < CC) ? ol[lane + 32] : -CUDART_INF_F;
        float l2 = (lane + 64 < CC) ? ol[lane + 64] : -CUDART_INF_F;

        float m = fmaxf(l0, fmaxf(l1, l2));
        #pragma unroll
        for (int o = 16; o; o >>= 1) m = fmaxf(m, __shfl_xor_sync(0xffffffffu, m, o));

        float s = __expf(l0 - m);
        if (lane + 32 < CC) s += __expf(l1 - m);
        if (lane + 64 < CC) s += __expf(l2 - m);
        #pragma unroll
        for (int o = 16; o; o >>= 1) s += __shfl_xor_sync(0xffffffffu, s, o);

        float bv = l0; int bi = lane;
        if (lane + 32 < CC - 1 && l1 > bv) { bv = l1; bi = lane + 32; }
        if (lane + 64 < CC - 1 && l2 > bv) { bv = l2; bi = lane + 64; }
        #pragma unroll
        for (int o = 16; o; o >>= 1) {
            float ov = __shfl_xor_sync(0xffffffffu, bv, o);
            int   oi = __shfl_xor_sync(0xffffffffu, bi, o);
            if (ov > bv || (ov == bv && oi < bi)) { bv = ov; bi = oi; }
        }
        const float obj_score = __fdividef(__expf(bv - m), s);
        const int   label = bi;

        // hoi scores = sigmoid(verb) * obj_score * cmat_bit(label, v)
        const float* vl = verb_logits + (size_t)gq * VV;
        float* ho = out + OFF_HOI + (size_t)gq * VV;
        const unsigned cb0 = cbits[label][0], cb1 = cbits[label][1];
        const unsigned cb2 = cbits[label][2], cb3 = cbits[label][3];
        float mx = -CUDART_INF_F;
        #pragma unroll
        for (int k = 0; k < 4; k++) {
            int v = lane + 32 * k;
            if (v < VV) {
                unsigned cw = (k == 0) ? cb0 : (k == 1) ? cb1 : (k == 2) ? cb2 : cb3;
                float bit = (float)((cw >> lane) & 1u);
                float e = __expf(-vl[v]);
                float sig = __fdividef(1.0f, 1.0f + e);
                float h = sig * obj_score * bit;
                ho[v] = h;
                mx = fmaxf(mx, h);
            }
        }
        #pragma unroll
        for (int o = 16; o; o >>= 1) mx = fmaxf(mx, __shfl_xor_sync(0xffffffffu, mx, o));

        if (lane == 0) {
            sh_max[q] = mx;
            sh_lab[q] = label;
            out[OFF_LAB + gq] = (float)label;
        }

        // boxes: cxcywh -> xyxy scaled; keep in shared + write to gmem
        if (lane < 8) {
            const int kk = lane & 3;
            const float* bx = ((lane < 4) ? sub_in : obj_in) + (size_t)gq * 4;
            float c = bx[kk & 1];
            float d = bx[(kk & 1) + 2];
            float sc = (kk & 1) ? img_h : img_w;
            float val = ((kk < 2) ? (c - 0.5f * d) : (c + 0.5f * d)) * sc;
            sh_box[q][lane] = val;
            out[((lane < 4) ? OFF_SUB : OFF_OBJ) + (size_t)gq * 4 + kk] = val;
        }
    }
    __syncthreads();

    // ---- Phase B1: stable descending rank, j-range split across two groups ----
    {
        int g = (tid >= 128);
        int q = g ? tid - 128 : tid;
        if (q < QQ) {
            float mine = sh_max[q];
            int r = 0;
            int j0 = g ? 50 : 0, j1 = g ? QQ : 50;
            #pragma unroll 5
            for (int j = j0; j < j1; j++) {
                float o = sh_max[j];
                r += (o > mine) || (o == mine && j < q);
            }
            rpart[g][q] = (short)r;
        }
    }
    __syncthreads();

    // ---- Phase B2: scatter into sorted order + label mask table ----
    if (tid < QQ) {
        int r = rpart[0][tid] + rpart[1][tid];
        float sx1 = sh_box[tid][0], sy1 = sh_box[tid][1];
        float sx2 = sh_box[tid][2], sy2 = sh_box[tid][3];
        float ox1 = sh_box[tid][4], oy1 = sh_box[tid][5];
        float ox2 = sh_box[tid][6], oy2 = sh_box[tid][7];
        r_s[0][r] = sx1; r_s[1][r] = sy1; r_s[2][r] = sx2; r_s[3][r] = sy2;
        r_s[4][r] = (sx2 - sx1 + 1.0f) * (sy2 - sy1 + 1.0f);
        r_o[0][r] = ox1; r_o[1][r] = oy1; r_o[2][r] = ox2; r_o[3][r] = oy2;
        r_o[4][r] = (ox2 - ox1 + 1.0f) * (oy2 - oy1 + 1.0f);
        int labv = sh_lab[tid];
        r_lab[r]  = labv;
        s_orig[r] = tid;
        atomicOr(&lmask[labv][r >> 5], 1u << (r & 31));
    }
    __syncthreads();

    // ---- Phase B3: compact same-label (i, j>i) pairs ----
    if (tid < QQ) {
        const int i = tid;
        const unsigned* lm = lmask[r_lab[i]];
        unsigned w[4];
        #pragma unroll
        for (int k = 0; k < 4; k++) {
            int d = i - 32 * k;
            unsigned gt = (d < 0) ? 0xFFFFFFFFu
                        : ((d >= 31) ? 0u : ~((2u << d) - 1u));
            w[k] = lm[k] & gt;
        }
        int nb = __popc(w[0]) + __popc(w[1]) + __popc(w[2]) + __popc(w[3]);
        if (nb) {
            int off = atomicAdd(&npairs, nb);
            #pragma unroll
            for (int k = 0; k < 4; k++) {
                unsigned word = w[k];
                while (word) {
                    int bit = __ffs(word) - 1;
                    word &= word - 1;
                    plist[off++] = make_ushort2((unsigned short)i,
                                                (unsigned short)(32 * k + bit));
                }
            }
        }
    }
    __syncthreads();

    // ---- Phase B4: evaluate pairs (expected ~62 per image) ----
    const int np = npairs;
    for (int p = tid; p < np; p += 256) {
        ushort2 pr = plist[p];
        int i = pr.x, j = pr.y;
        float w  = fmaxf(0.0f, fminf(r_s[2][i], r_s[2][j]) - fmaxf(r_s[0][i], r_s[0][j]) + 1.0f);
        float h  = fmaxf(0.0f, fminf(r_s[3][i], r_s[3][j]) - fmaxf(r_s[1][i], r_s[1][j]) + 1.0f);
        float is = w * h;
        float us = r_s[4][i] + r_s[4][j] - is;
        float w2 = fmaxf(0.0f, fminf(r_o[2][i], r_o[2][j]) - fmaxf(r_o[0][i], r_o[0][j]) + 1.0f);
        float h2 = fmaxf(0.0f, fminf(r_o[3][i], r_o[3][j]) - fmaxf(r_o[1][i], r_o[1][j]) + 1.0f);
        float io = w2 * h2;
        float uo = r_o[4][i] + r_o[4][j] - io;
        if ((is * is) * io > 0.49f * (us * us) * uo)   // == (is/us)*sqrt(io/uo) > 0.7
            atomicOr(&supmat[i][j >> 5], 1u << (j & 31));
    }
    __syncthreads();

    // ---- Phase B5: sequential greedy suppression (1 thread) ----
    if (tid == 0) {
        unsigned w0 = 0, w1 = 0, w2 = 0, w3 = 0;
        if (np) {
            uint4 row = *(const uint4*)&supmat[0][0];
            #pragma unroll 4
            for (int i = 0; i < QQ; i++) {
                uint4 next = (i + 1 < QQ) ? *(const uint4*)&supmat[i + 1][0]
                                          : make_uint4(0,0,0,0);
                unsigned wi = (i < 32) ? w0 : (i < 64) ? w1 : (i < 96) ? w2 : w3;
                if (!((wi >> (i & 31)) & 1u)) {
                    w0 |= row.x; w1 |= row.y; w2 |= row.z; w3 |= row.w;
                }
                row = next;
            }
        }
        suppw[0] = w0; suppw[1] = w1; suppw[2] = w2; suppw[3] = w3;
    }
    __syncthreads();

    if (tid < QQ) {
        bool suppressed = (suppw[tid >> 5] >> (tid & 31)) & 1u;
        out[OFF_KEEP + b * QQ + s_orig[tid]] = suppressed ? 0.0f : 1.0f;
    }
}

// ---------------------------------------------------------------------------
extern "C" void kernel_launch(void* const* d_in, const int* in_sizes, int n_in,
                              void* d_out, int out_size)
{
    const float* obj_logits  = (const float*)d_in[0];
    const float* verb_logits = (const float*)d_in[1];
    const float* sub_boxes   = (const float*)d_in[2];
    const float* obj_boxes   = (const float*)d_in[3];
    const float* correct_mat = (const float*)d_in[4];
    const int*   target_sz   = (const int*)d_in[5];
    float* out = (float*)d_out;

    k_fused<<<BB, 256>>>(obj_logits, verb_logits, sub_boxes, obj_boxes,
                         correct_mat, target_sz, out);
}

// round 14
// speedup vs baseline: 1.2901x; 1.2901x over previous
#include <cuda_runtime.h>
#include <cuda_bf16.h>
#include <math_constants.h>

#define BB 512
#define QQ 100
#define CC 81
#define VV 117
#define NQ (BB*QQ)

// Output layout (flattened tuple, float32):
// hoi_scores [B,Q,V] | obj_labels [B,Q] | sub_boxes [B,Q,4] | obj_boxes [B,Q,4] | keep [B,Q]
#define OFF_HOI  0ull
#define OFF_LAB  ((unsigned long long)NQ * VV)
#define OFF_SUB  (OFF_LAB + (unsigned long long)NQ)
#define OFF_OBJ  (OFF_SUB + (unsigned long long)NQ * 4)
#define OFF_KEEP (OFF_OBJ + (unsigned long long)NQ * 4)

// Scratch
__device__ float g_maxsc[NQ];
__device__ float g_cmatT[CC * VV];   // transposed correct_mat: [C][V]

// ---------------------------------------------------------------------------
// Kernel 0: transpose correct_mat [V,C] -> [C,V].
// Grid >= 148 so every SM gets work (one LDG+STG deep; latency-bound).
// ---------------------------------------------------------------------------
__global__ __launch_bounds__(64)
void k0_transpose(const float* __restrict__ cmat)
{
    int idx = blockIdx.x * 64 + threadIdx.x;    // idx = v*CC + c (coalesced read)
    if (idx < CC * VV) {
        int v = idx / CC;
        int c = idx - v * CC;
        g_cmatT[c * VV + v] = cmat[idx];
    }
}

// ---------------------------------------------------------------------------
// Kernel 1: per-query scoring + boxes. One warp per query, 8 warps per block.
// ---------------------------------------------------------------------------
__global__ __launch_bounds__(256)
void k1_score(const float* __restrict__ obj_logits,
              const float* __restrict__ verb_logits,
              const float* __restrict__ sub_in,
              const float* __restrict__ obj_in,
              const int* __restrict__ ts,         // [B, 2] (h, w) int32
              float* __restrict__ out)
{
    const int warp = threadIdx.x >> 5;
    const int lane = threadIdx.x & 31;
    const int gq = blockIdx.x * 8 + warp;
    if (gq >= NQ) return;
    const int b = gq / QQ;

    // ---- softmax over 81 obj logits; max/argmax over first 80 ----
    const float* ol = obj_logits + (size_t)gq * CC;
    float l0 = ol[lane];
    float l1 = (lane + 32 < CC) ? ol[lane + 32] : -CUDART_INF_F;
    float l2 = (lane + 64 < CC) ? ol[lane + 64] : -CUDART_INF_F;

    float m = fmaxf(l0, fmaxf(l1, l2));
    #pragma unroll
    for (int o = 16; o; o >>= 1) m = fmaxf(m, __shfl_xor_sync(0xffffffffu, m, o));

    float s = __expf(l0 - m);
    if (lane + 32 < CC) s += __expf(l1 - m);
    if (lane + 64 < CC) s += __expf(l2 - m);
    #pragma unroll
    for (int o = 16; o; o >>= 1) s += __shfl_xor_sync(0xffffffffu, s, o);

    // argmax over classes [0, 80)
    float bv = l0; int bi = lane;
    if (lane + 32 < CC - 1 && l1 > bv) { bv = l1; bi = lane + 32; }
    if (lane + 64 < CC - 1 && l2 > bv) { bv = l2; bi = lane + 64; }
    #pragma unroll
    for (int o = 16; o; o >>= 1) {
        float ov = __shfl_xor_sync(0xffffffffu, bv, o);
        int   oi = __shfl_xor_sync(0xffffffffu, bi, o);
        if (ov > bv || (ov == bv && oi < bi)) { bv = ov; bi = oi; }
    }
    const float obj_score = __fdividef(__expf(bv - m), s);
    const int   label = bi;

    // ---- hoi scores = sigmoid(verb) * obj_score * cmatT[label][v] ----
    const float* vl = verb_logits + (size_t)gq * VV;
    const float* cm = g_cmatT + (size_t)label * VV;
    float* ho = out + OFF_HOI + (size_t)gq * VV;
    float mx = -CUDART_INF_F;
    #pragma unroll
    for (int v = lane; v < VV; v += 32) {
        float e = __expf(-vl[v]);
        float sig = __fdividef(1.0f, 1.0f + e);
        float h = sig * obj_score * cm[v];
        ho[v] = h;
        mx = fmaxf(mx, h);
    }
    #pragma unroll
    for (int o = 16; o; o >>= 1) mx = fmaxf(mx, __shfl_xor_sync(0xffffffffu, mx, o));

    if (lane == 0) {
        g_maxsc[gq] = mx;
        out[OFF_LAB + gq] = (float)label;
    }

    // ---- boxes: cxcywh -> xyxy, * [w,h,w,h] ----
    if (lane < 8) {
        const int kk = lane & 3;
        const float* bx = ((lane < 4) ? sub_in : obj_in) + (size_t)gq * 4;
        float c = bx[kk & 1];
        float d = bx[(kk & 1) + 2];
        float sc = (kk & 1) ? (float)ts[b * 2 + 0] : (float)ts[b * 2 + 1];
        float val = ((kk < 2) ? (c - 0.5f * d) : (c + 0.5f * d)) * sc;
        out[((lane < 4) ? OFF_SUB : OFF_OBJ) + (size_t)gq * 4 + kk] = val;
    }
}

// ---------------------------------------------------------------------------
// Kernel 2: per-image NMS with pair compaction. Box/label loads issued into
// registers BEFORE the rank loop so DRAM latency overlaps rank compute.
// ---------------------------------------------------------------------------
#define MAXP (QQ*(QQ-1)/2)   // 4950, worst case all labels equal

__global__ __launch_bounds__(256, 4)
void k2_nms(float* __restrict__ out)
{
    const int b   = blockIdx.x;
    const int tid = threadIdx.x;

    __shared__ float sc[QQ];
    __shared__ short rpart[2][QQ];
    __shared__ int   s_orig[QQ];
    __shared__ int   r_lab[QQ];
    __shared__ float r_s[5][QQ];           // sorted sub: x1,y1,x2,y2,area
    __shared__ float r_o[5][QQ];           // sorted obj
    __shared__ unsigned lmask[CC][4];      // per-label bitmask of sorted positions
    __shared__ unsigned supmat[QQ][4];
    __shared__ unsigned suppw[4];
    __shared__ int npairs;
    __shared__ ushort2 plist[MAXP];

    // ---- issue ALL global loads up front (latency hidden under rank) ----
    float4 sb = make_float4(0,0,0,0), ob = make_float4(0,0,0,0);
    int labv = 0;
    if (tid < QQ) {
        const size_t base = (size_t)(b * QQ + tid);
        sc[tid] = g_maxsc[base];
        sb   = *(const float4*)(out + OFF_SUB + base * 4);
        ob   = *(const float4*)(out + OFF_OBJ + base * 4);
        labv = (int)out[OFF_LAB + base];
    }
    for (int t = tid; t < CC * 4; t += 256) ((unsigned*)lmask)[t] = 0u;
    for (int t = tid; t < QQ * 4; t += 256) ((unsigned*)supmat)[t] = 0u;
    if (tid == 0) npairs = 0;
    __syncthreads();

    // ---- stable descending rank, j-range split across two groups ----
    {
        int g = (tid >= 128);
        int q = g ? tid - 128 : tid;
        if (q < QQ) {
            float mine = sc[q];
            int r = 0;
            int j0 = g ? 50 : 0, j1 = g ? QQ : 50;
            #pragma unroll 5
            for (int j = j0; j < j1; j++) {
                float o = sc[j];
                r += (o > mine) || (o == mine && j < q);
            }
            rpart[g][q] = (short)r;
        }
    }
    __syncthreads();

    // ---- scatter (from registers) into sorted order + label mask table ----
    if (tid < QQ) {
        int r = rpart[0][tid] + rpart[1][tid];
        r_s[0][r] = sb.x; r_s[1][r] = sb.y; r_s[2][r] = sb.z; r_s[3][r] = sb.w;
        r_s[4][r] = (sb.z - sb.x + 1.0f) * (sb.w - sb.y + 1.0f);
        r_o[0][r] = ob.x; r_o[1][r] = ob.y; r_o[2][r] = ob.z; r_o[3][r] = ob.w;
        r_o[4][r] = (ob.z - ob.x + 1.0f) * (ob.w - ob.y + 1.0f);
        r_lab[r]  = labv;
        s_orig[r] = tid;
        atomicOr(&lmask[labv][r >> 5], 1u << (r & 31));
    }
    __syncthreads();

    // ---- compact same-label (i, j>i) pairs into a worklist ----
    if (tid < QQ) {
        const int i = tid;
        const unsigned* lm = lmask[r_lab[i]];
        unsigned w[4];
        #pragma unroll
        for (int k = 0; k < 4; k++) {
            int d = i - 32 * k;
            unsigned gt = (d < 0) ? 0xFFFFFFFFu
                        : ((d >= 31) ? 0u : ~((2u << d) - 1u));
            w[k] = lm[k] & gt;
        }
        int nb = __popc(w[0]) + __popc(w[1]) + __popc(w[2]) + __popc(w[3]);
        if (nb) {
            int off = atomicAdd(&npairs, nb);
            #pragma unroll
            for (int k = 0; k < 4; k++) {
                unsigned word = w[k];
                while (word) {
                    int bit = __ffs(word) - 1;
                    word &= word - 1;
                    plist[off++] = make_ushort2((unsigned short)i,
                                                (unsigned short)(32 * k + bit));
                }
            }
        }
    }
    __syncthreads();

    // ---- evaluate pairs (expected ~62 per image) ----
    const int np = npairs;
    for (int p = tid; p < np; p += 256) {
        ushort2 pr = plist[p];
        int i = pr.x, j = pr.y;
        float w  = fmaxf(0.0f, fminf(r_s[2][i], r_s[2][j]) - fmaxf(r_s[0][i], r_s[0][j]) + 1.0f);
        float h  = fmaxf(0.0f, fminf(r_s[3][i], r_s[3][j]) - fmaxf(r_s[1][i], r_s[1][j]) + 1.0f);
        float is = w * h;
        float us = r_s[4][i] + r_s[4][j] - is;
        float w2 = fmaxf(0.0f, fminf(r_o[2][i], r_o[2][j]) - fmaxf(r_o[0][i], r_o[0][j]) + 1.0f);
        float h2 = fmaxf(0.0f, fminf(r_o[3][i], r_o[3][j]) - fmaxf(r_o[1][i], r_o[1][j]) + 1.0f);
        float io = w2 * h2;
        float uo = r_o[4][i] + r_o[4][j] - io;
        if ((is * is) * io > 0.49f * (us * us) * uo)   // == (is/us)*sqrt(io/uo) > 0.7
            atomicOr(&supmat[i][j >> 5], 1u << (j & 31));
    }
    __syncthreads();

    // ---- sequential greedy suppression (1 thread, prefetched rows) ----
    if (tid == 0) {
        unsigned w0 = 0, w1 = 0, w2 = 0, w3 = 0;
        if (np) {
            uint4 row = *(const uint4*)&supmat[0][0];
            #pragma unroll 4
            for (int i = 0; i < QQ; i++) {
                uint4 next = (i + 1 < QQ) ? *(const uint4*)&supmat[i + 1][0]
                                          : make_uint4(0,0,0,0);
                unsigned wi = (i < 32) ? w0 : (i < 64) ? w1 : (i < 96) ? w2 : w3;
                if (!((wi >> (i & 31)) & 1u)) {
                    w0 |= row.x; w1 |= row.y; w2 |= row.z; w3 |= row.w;
                }
                row = next;
            }
        }
        suppw[0] = w0; suppw[1] = w1; suppw[2] = w2; suppw[3] = w3;
    }
    __syncthreads();

    if (tid < QQ) {
        bool suppressed = (suppw[tid >> 5] >> (tid & 31)) & 1u;
        out[OFF_KEEP + b * QQ + s_orig[tid]] = suppressed ? 0.0f : 1.0f;
    }
}

// ---------------------------------------------------------------------------
extern "C" void kernel_launch(void* const* d_in, const int* in_sizes, int n_in,
                              void* d_out, int out_size)
{
    const float* obj_logits  = (const float*)d_in[0];
    const float* verb_logits = (const float*)d_in[1];
    const float* sub_boxes   = (const float*)d_in[2];
    const float* obj_boxes   = (const float*)d_in[3];
    const float* correct_mat = (const float*)d_in[4];
    const int*   target_sz   = (const int*)d_in[5];
    float* out = (float*)d_out;

    k0_transpose<<<(CC * VV + 63) / 64, 64>>>(correct_mat);
    k1_score<<<NQ / 8, 256>>>(obj_logits, verb_logits, sub_boxes, obj_boxes,
                              target_sz, out);
    k2_nms<<<BB, 256>>>(out);
}

// round 15
// speedup vs baseline: 1.3022x; 1.0094x over previous
#include <cuda_runtime.h>
#include <cuda_bf16.h>
#include <math_constants.h>

#define BB 512
#define QQ 100
#define CC 81
#define VV 117
#define NQ (BB*QQ)

// Output layout (flattened tuple, float32):
// hoi_scores [B,Q,V] | obj_labels [B,Q] | sub_boxes [B,Q,4] | obj_boxes [B,Q,4] | keep [B,Q]
#define OFF_HOI  0ull
#define OFF_LAB  ((unsigned long long)NQ * VV)
#define OFF_SUB  (OFF_LAB + (unsigned long long)NQ)
#define OFF_OBJ  (OFF_SUB + (unsigned long long)NQ * 4)
#define OFF_KEEP (OFF_OBJ + (unsigned long long)NQ * 4)

// Scratch
__device__ float g_maxsc[NQ];
__device__ float g_cmatT[CC * VV];   // transposed correct_mat: [C][V]

// ---------------------------------------------------------------------------
// Kernel 0: transpose correct_mat [V,C] -> [C,V].
// Runs CONCURRENTLY with k1's softmax phase via PDL.
// ---------------------------------------------------------------------------
__global__ __launch_bounds__(256)
void k0_transpose(const float* __restrict__ cmat)
{
    int idx = blockIdx.x * 256 + threadIdx.x;   // idx = v*CC + c (coalesced read)
    if (idx < CC * VV) {
        int v = idx / CC;
        int c = idx - v * CC;
        g_cmatT[c * VV + v] = cmat[idx];
    }
}

// ---------------------------------------------------------------------------
// Kernel 1: per-query scoring + boxes. One warp per query, 8 warps per block.
// Launched with PDL: starts alongside k0; grid-dependency sync only before
// the g_cmatT read (softmax/argmax phase needs no k0 output).
// ---------------------------------------------------------------------------
__global__ __launch_bounds__(256)
void k1_score(const float* __restrict__ obj_logits,
              const float* __restrict__ verb_logits,
              const float* __restrict__ sub_in,
              const float* __restrict__ obj_in,
              const int* __restrict__ ts,         // [B, 2] (h, w) int32
              float* __restrict__ out)
{
    const int warp = threadIdx.x >> 5;
    const int lane = threadIdx.x & 31;
    const int gq = blockIdx.x * 8 + warp;
    if (gq >= NQ) { cudaGridDependencySynchronize(); return; }
    const int b = gq / QQ;

    // ---- softmax over 81 obj logits; max/argmax over first 80 ----
    const float* ol = obj_logits + (size_t)gq * CC;
    float l0 = ol[lane];
    float l1 = (lane + 32 < CC) ? ol[lane + 32] : -CUDART_INF_F;
    float l2 = (lane + 64 < CC) ? ol[lane + 64] : -CUDART_INF_F;

    float m = fmaxf(l0, fmaxf(l1, l2));
    #pragma unroll
    for (int o = 16; o; o >>= 1) m = fmaxf(m, __shfl_xor_sync(0xffffffffu, m, o));

    float s = __expf(l0 - m);
    if (lane + 32 < CC) s += __expf(l1 - m);
    if (lane + 64 < CC) s += __expf(l2 - m);
    #pragma unroll
    for (int o = 16; o; o >>= 1) s += __shfl_xor_sync(0xffffffffu, s, o);

    // argmax over classes [0, 80)
    float bv = l0; int bi = lane;
    if (lane + 32 < CC - 1 && l1 > bv) { bv = l1; bi = lane + 32; }
    if (lane + 64 < CC - 1 && l2 > bv) { bv = l2; bi = lane + 64; }
    #pragma unroll
    for (int o = 16; o; o >>= 1) {
        float ov = __shfl_xor_sync(0xffffffffu, bv, o);
        int   oi = __shfl_xor_sync(0xffffffffu, bi, o);
        if (ov > bv || (ov == bv && oi < bi)) { bv = ov; bi = oi; }
    }
    const float obj_score = __fdividef(__expf(bv - m), s);
    const int   label = bi;

    // ---- boxes: cxcywh -> xyxy, * [w,h,w,h] (independent of k0) ----
    if (lane < 8) {
        const int kk = lane & 3;
        const float* bx = ((lane < 4) ? sub_in : obj_in) + (size_t)gq * 4;
        float c = bx[kk & 1];
        float d = bx[(kk & 1) + 2];
        float sc = (kk & 1) ? (float)ts[b * 2 + 0] : (float)ts[b * 2 + 1];
        float val = ((kk < 2) ? (c - 0.5f * d) : (c + 0.5f * d)) * sc;
        out[((lane < 4) ? OFF_SUB : OFF_OBJ) + (size_t)gq * 4 + kk] = val;
    }

    // ---- wait for k0 (transpose) before touching g_cmatT ----
    cudaGridDependencySynchronize();

    // ---- hoi scores = sigmoid(verb) * obj_score * cmatT[label][v] ----
    const float* vl = verb_logits + (size_t)gq * VV;
    const float* cm = g_cmatT + (size_t)label * VV;
    float* ho = out + OFF_HOI + (size_t)gq * VV;
    float mx = -CUDART_INF_F;
    #pragma unroll
    for (int v = lane; v < VV; v += 32) {
        float e = __expf(-vl[v]);
        float sig = __fdividef(1.0f, 1.0f + e);
        float h = sig * obj_score * cm[v];
        ho[v] = h;
        mx = fmaxf(mx, h);
    }
    #pragma unroll
    for (int o = 16; o; o >>= 1) mx = fmaxf(mx, __shfl_xor_sync(0xffffffffu, mx, o));

    if (lane == 0) {
        g_maxsc[gq] = mx;
        out[OFF_LAB + gq] = (float)label;
    }
}

// ---------------------------------------------------------------------------
// Kernel 2: per-image NMS with pair compaction. Launched with PDL: shared
// init overlaps k1's tail; grid-dependency sync before the dependent loads.
// ---------------------------------------------------------------------------
#define MAXP (QQ*(QQ-1)/2)   // 4950, worst case all labels equal

__global__ __launch_bounds__(256, 4)
void k2_nms(float* __restrict__ out)
{
    const int b   = blockIdx.x;
    const int tid = threadIdx.x;

    __shared__ float sc[QQ];
    __shared__ short rpart[2][QQ];
    __shared__ int   s_orig[QQ];
    __shared__ int   r_lab[QQ];
    __shared__ float r_s[5][QQ];           // sorted sub: x1,y1,x2,y2,area
    __shared__ float r_o[5][QQ];           // sorted obj
    __shared__ unsigned lmask[CC][4];      // per-label bitmask of sorted positions
    __shared__ unsigned supmat[QQ][4];
    __shared__ unsigned suppw[4];
    __shared__ int npairs;
    __shared__ ushort2 plist[MAXP];

    // ---- shared init overlaps k1 tail (no global reads yet) ----
    for (int t = tid; t < CC * 4; t += 256) ((unsigned*)lmask)[t] = 0u;
    for (int t = tid; t < QQ * 4; t += 256) ((unsigned*)supmat)[t] = 0u;
    if (tid == 0) npairs = 0;

    // ---- wait for k1's outputs, then issue ALL global loads up front ----
    cudaGridDependencySynchronize();

    float4 sb = make_float4(0,0,0,0), ob = make_float4(0,0,0,0);
    int labv = 0;
    if (tid < QQ) {
        const size_t base = (size_t)(b * QQ + tid);
        sc[tid] = g_maxsc[base];
        sb   = *(const float4*)(out + OFF_SUB + base * 4);
        ob   = *(const float4*)(out + OFF_OBJ + base * 4);
        labv = (int)out[OFF_LAB + base];
    }
    __syncthreads();

    // ---- stable descending rank, j-range split across two groups ----
    {
        int g = (tid >= 128);
        int q = g ? tid - 128 : tid;
        if (q < QQ) {
            float mine = sc[q];
            int r = 0;
            int j0 = g ? 50 : 0, j1 = g ? QQ : 50;
            #pragma unroll 5
            for (int j = j0; j < j1; j++) {
                float o = sc[j];
                r += (o > mine) || (o == mine && j < q);
            }
            rpart[g][q] = (short)r;
        }
    }
    __syncthreads();

    // ---- scatter (from registers) into sorted order + label mask table ----
    if (tid < QQ) {
        int r = rpart[0][tid] + rpart[1][tid];
        r_s[0][r] = sb.x; r_s[1][r] = sb.y; r_s[2][r] = sb.z; r_s[3][r] = sb.w;
        r_s[4][r] = (sb.z - sb.x + 1.0f) * (sb.w - sb.y + 1.0f);
        r_o[0][r] = ob.x; r_o[1][r] = ob.y; r_o[2][r] = ob.z; r_o[3][r] = ob.w;
        r_o[4][r] = (ob.z - ob.x + 1.0f) * (ob.w - ob.y + 1.0f);
        r_lab[r]  = labv;
        s_orig[r] = tid;
        atomicOr(&lmask[labv][r >> 5], 1u << (r & 31));
    }
    __syncthreads();

    // ---- compact same-label (i, j>i) pairs into a worklist ----
    if (tid < QQ) {
        const int i = tid;
        const unsigned* lm = lmask[r_lab[i]];
        unsigned w[4];
        #pragma unroll
        for (int k = 0; k < 4; k++) {
            int d = i - 32 * k;
            unsigned gt = (d < 0) ? 0xFFFFFFFFu
                        : ((d >= 31) ? 0u : ~((2u << d) - 1u));
            w[k] = lm[k] & gt;
        }
        int nb = __popc(w[0]) + __popc(w[1]) + __popc(w[2]) + __popc(w[3]);
        if (nb) {
            int off = atomicAdd(&npairs, nb);
            #pragma unroll
            for (int k = 0; k < 4; k++) {
                unsigned word = w[k];
                while (word) {
                    int bit = __ffs(word) - 1;
                    word &= word - 1;
                    plist[off++] = make_ushort2((unsigned short)i,
                                                (unsigned short)(32 * k + bit));
                }
            }
        }
    }
    __syncthreads();

    // ---- evaluate pairs (expected ~62 per image) ----
    const int np = npairs;
    for (int p = tid; p < np; p += 256) {
        ushort2 pr = plist[p];
        int i = pr.x, j = pr.y;
        float w  = fmaxf(0.0f, fminf(r_s[2][i], r_s[2][j]) - fmaxf(r_s[0][i], r_s[0][j]) + 1.0f);
        float h  = fmaxf(0.0f, fminf(r_s[3][i], r_s[3][j]) - fmaxf(r_s[1][i], r_s[1][j]) + 1.0f);
        float is = w * h;
        float us = r_s[4][i] + r_s[4][j] - is;
        float w2 = fmaxf(0.0f, fminf(r_o[2][i], r_o[2][j]) - fmaxf(r_o[0][i], r_o[0][j]) + 1.0f);
        float h2 = fmaxf(0.0f, fminf(r_o[3][i], r_o[3][j]) - fmaxf(r_o[1][i], r_o[1][j]) + 1.0f);
        float io = w2 * h2;
        float uo = r_o[4][i] + r_o[4][j] - io;
        if ((is * is) * io > 0.49f * (us * us) * uo)   // == (is/us)*sqrt(io/uo) > 0.7
            atomicOr(&supmat[i][j >> 5], 1u << (j & 31));
    }
    __syncthreads();

    // ---- sequential greedy suppression (1 thread, prefetched rows) ----
    if (tid == 0) {
        unsigned w0 = 0, w1 = 0, w2 = 0, w3 = 0;
        if (np) {
            uint4 row = *(const uint4*)&supmat[0][0];
            #pragma unroll 4
            for (int i = 0; i < QQ; i++) {
                uint4 next = (i + 1 < QQ) ? *(const uint4*)&supmat[i + 1][0]
                                          : make_uint4(0,0,0,0);
                unsigned wi = (i < 32) ? w0 : (i < 64) ? w1 : (i < 96) ? w2 : w3;
                if (!((wi >> (i & 31)) & 1u)) {
                    w0 |= row.x; w1 |= row.y; w2 |= row.z; w3 |= row.w;
                }
                row = next;
            }
        }
        suppw[0] = w0; suppw[1] = w1; suppw[2] = w2; suppw[3] = w3;
    }
    __syncthreads();

    if (tid < QQ) {
        bool suppressed = (suppw[tid >> 5] >> (tid & 31)) & 1u;
        out[OFF_KEEP + b * QQ + s_orig[tid]] = suppressed ? 0.0f : 1.0f;
    }
}

// ---------------------------------------------------------------------------
extern "C" void kernel_launch(void* const* d_in, const int* in_sizes, int n_in,
                              void* d_out, int out_size)
{
    const float* obj_logits  = (const float*)d_in[0];
    const float* verb_logits = (const float*)d_in[1];
    const float* sub_boxes   = (const float*)d_in[2];
    const float* obj_boxes   = (const float*)d_in[3];
    const float* correct_mat = (const float*)d_in[4];
    const int*   target_sz   = (const int*)d_in[5];
    float* out = (float*)d_out;

    // k0: normal launch
    k0_transpose<<<(CC * VV + 255) / 256, 256>>>(correct_mat);

    // PDL attribute: allow k1/k2 to launch while their predecessor runs;
    // device-side cudaGridDependencySynchronize() enforces the data hand-off.
    cudaLaunchAttribute attr[1];
    attr[0].id = cudaLaunchAttributeProgrammaticStreamSerialization;
    attr[0].val.programmaticStreamSerializationAllowed = 1;

    {
        cudaLaunchConfig_t cfg = {};
        cfg.gridDim  = dim3(NQ / 8);
        cfg.blockDim = dim3(256);
        cfg.attrs    = attr;
        cfg.numAttrs = 1;
        cudaLaunchKernelEx(&cfg, k1_score, obj_logits, verb_logits,
                           sub_boxes, obj_boxes, target_sz, out);
    }
    {
        cudaLaunchConfig_t cfg = {};
        cfg.gridDim  = dim3(BB);
        cfg.blockDim = dim3(256);
        cfg.attrs    = attr;
        cfg.numAttrs = 1;
        cudaLaunchKernelEx(&cfg, k2_nms, out);
    }
}